// round 11
// baseline (speedup 1.0000x reference)
#include <cuda_runtime.h>

// Graph_Learn: S[n,i,j] = exp(relu(sum_f |xm[n,i,f]-xm[n,j,f]|*a[f])) / colsum_i
// N=8, T=8 (slice t=4), V=512, F=64. Output (8,512,512) fp32.
// Single cooperative persistent kernel (driver-guaranteed co-residency).
// R11: j-rows moved from registers (64 regs) to padded smem (stride 68,
// conflict-free per-lane LDS.128) -> 3 CTAs/SM, 24 warps, higher issue rate.

#define NB    8
#define TB    8
#define VB    512
#define FB    64
#define TS    64
#define NT    (VB / TS)                 // 8
#define NPAIR (NT * (NT + 1) / 2)       // 36
#define NBLK  (NPAIR * NB)              // 288 (<= 148 SMs * 3 CTA/SM)
#define XJS   68                        // padded j-row stride (68 % 32 == 4)

typedef unsigned long long ull;

__device__ float g_partial[NB * NT * VB];   // [n][d][col], each slot written once
__device__ ull   g_bar = 0ull;              // monotone generation counter

__device__ __forceinline__ ull addx2(ull a, ull b) {
    ull r; asm("add.rn.f32x2 %0, %1, %2;" : "=l"(r) : "l"(a), "l"(b)); return r;
}
__device__ __forceinline__ ull fmax2k(ull a, ull b, ull c) {
    ull r; asm("fma.rn.f32x2 %0, %1, %2, %3;" : "=l"(r) : "l"(a), "l"(b), "l"(c)); return r;
}
__device__ __forceinline__ float sum2(ull a) {
    float lo, hi; asm("mov.b64 {%0, %1}, %2;" : "=f"(lo), "=f"(hi) : "l"(a)); return lo + hi;
}

// smem (floats): xi[64][64] | xjp[64][68] | ev[64][65] | sa[64] | ps[4][64] | invj[64] | invi[64]
#define SMA_XJP  (TS * FB)                  // 4096
#define SMA_EV   (SMA_XJP + TS * XJS)       // 4096+4352
#define SMA_A    (SMA_EV + TS * 65)
#define SMA_PS   (SMA_A + FB)
#define SMA_IJ   (SMA_PS + 4 * TS)
#define SMA_II   (SMA_IJ + TS)
#define SMA_FLOATS (SMA_II + TS)            // 13056 floats = 52224 B

__global__ __launch_bounds__(256, 3)
void graph_learn_fused(const float* __restrict__ x,
                       const float* __restrict__ a,
                       float* __restrict__ out) {
    extern __shared__ float sm[];
    float* xi   = sm;                 // [64][64]  (broadcast rows)
    float* xjp  = sm + SMA_XJP;       // [64][68]  (negated j-rows, per-lane)
    float* ev   = sm + SMA_EV;        // [64][65] padded
    float* sa   = sm + SMA_A;         // [64]
    float* ps   = sm + SMA_PS;        // [4][64]
    float* invj = sm + SMA_IJ;        // [64]
    float* invi = sm + SMA_II;        // [64]

    const int n   = blockIdx.y;
    const int tid = threadIdx.x;

    // decode upper-tri tile pair (ti <= tj)
    int ti = 0, rem = blockIdx.x;
    while (rem >= NT - ti) { rem -= NT - ti; ti++; }
    const int tj = ti + rem;

    const float* xbase = x + ((size_t)n * TB + TB / 2) * VB * FB;
    {
        const float4* si = (const float4*)(xbase + ti * TS * FB);
        const float4* sj = (const float4*)(xbase + tj * TS * FB);
        float4* xi4 = (float4*)xi;
        for (int k = tid; k < TS * FB / 4; k += 256) {
            xi4[k] = si[k];
            float4 v = sj[k];                       // negate j-rows on store
            int row = k >> 4, c4 = k & 15;
            float4* dst = (float4*)(xjp + row * XJS + c4 * 4);
            dst->x = -v.x; dst->y = -v.y; dst->z = -v.z; dst->w = -v.w;
        }
        if (tid < FB / 4) ((float4*)sa)[tid] = ((const float4*)a)[tid];
    }
    __syncthreads();

    const int jl = tid & (TS - 1);   // j within tile (0..63)
    const int ig = tid >> 6;         // i-group (0..3)

    const ull ABSM = 0x7FFFFFFF7FFFFFFFULL;
    const ulonglong2* sa2 = (const ulonglong2*)sa;
    const ulonglong2* xr  = (const ulonglong2*)(xjp + jl * XJS);  // per-lane, conflict-free
    float csum = 0.f;

    // mainloop: 2 i-rows per iter, 4 packed accumulator chains; exp -> smem only
    #pragma unroll 1
    for (int it = 0; it < TS / 8; it++) {        // 8 iters
        const int i0 = (it * 4 + ig) * 2;        // warp-uniform
        const int i1 = i0 + 1;
        const ulonglong2* r0 = (const ulonglong2*)(xi + i0 * FB);
        const ulonglong2* r1 = (const ulonglong2*)(xi + i1 * FB);
        ull a00 = 0, a01 = 0, a10 = 0, a11 = 0;
        #pragma unroll
        for (int k = 0; k < FB / 4; k++) {
            ulonglong2 av  = sa2[k];
            ulonglong2 xjv = xr[k];
            ulonglong2 v0  = r0[k];
            ulonglong2 v1  = r1[k];
            ull d;
            d = addx2(v0.x, xjv.x) & ABSM; a00 = fmax2k(d, av.x, a00);
            d = addx2(v0.y, xjv.y) & ABSM; a01 = fmax2k(d, av.y, a01);
            d = addx2(v1.x, xjv.x) & ABSM; a10 = fmax2k(d, av.x, a10);
            d = addx2(v1.y, xjv.y) & ABSM; a11 = fmax2k(d, av.y, a11);
        }
        float s0 = sum2(a00) + sum2(a01);
        float s1 = sum2(a10) + sum2(a11);
        float e0 = __expf(fmaxf(s0, 0.f));
        float e1 = __expf(fmaxf(s1, 0.f));
        ev[i0 * 65 + jl] = e0;
        ev[i1 * 65 + jl] = e1;
        csum += e0 + e1;
    }

    // direct partial: rows ti-range, columns tj*64+jl -> slot [n][ti]
    ps[ig * TS + jl] = csum;
    __syncthreads();
    if (tid < TS) {
        float t = ps[tid] + ps[TS + tid] + ps[2 * TS + tid] + ps[3 * TS + tid];
        g_partial[(n * NT + ti) * VB + tj * TS + tid] = t;
    }

    const int il = tid & (TS - 1);
    const int jg = tid >> 6;
    if (ti != tj) {
        // transposed partial: rows tj-range, columns ti*64+il -> slot [n][tj]
        float rsum = 0.f;
        #pragma unroll
        for (int m = 0; m < TS / 4; m++) {
            rsum += ev[il * 65 + (m * 4 + jg)];   // stride-65: conflict-free
        }
        __syncthreads();                          // ps readers done
        ps[jg * TS + il] = rsum;
        __syncthreads();
        if (tid < TS) {
            float t = ps[tid] + ps[TS + tid] + ps[2 * TS + tid] + ps[3 * TS + tid];
            g_partial[(n * NT + tj) * VB + ti * TS + tid] = t;
        }
    }

    // ---- software grid barrier (generation counting, replay-safe;
    //      co-residency guaranteed by cooperative launch) ----
    __threadfence();
    __syncthreads();
    if (tid == 0) {
        ull my = atomicAdd(&g_bar, 1ull);
        ull target = (my / NBLK + 1ull) * (ull)NBLK;
        while (*((volatile ull*)&g_bar) < target) { __nanosleep(32); }
    }
    __syncthreads();
    __threadfence();

    // ---- column sums -> inverse norms ----
    if (tid < TS) {
        const float* p = g_partial + n * NT * VB + tj * TS + tid;
        float s = 0.f;
        #pragma unroll
        for (int d = 0; d < NT; d++) s += p[d * VB];
        invj[tid] = 1.0f / s;
    } else if (tid < 2 * TS && ti != tj) {
        const float* p = g_partial + n * NT * VB + ti * TS + (tid - TS);
        float s = 0.f;
        #pragma unroll
        for (int d = 0; d < NT; d++) s += p[d * VB];
        invi[tid - TS] = 1.0f / s;
    }
    __syncthreads();

    // ---- normalized writes (single gmem write per element) ----
    float* o = out + (size_t)n * VB * VB;
    {
        const float fj = invj[jl];
        #pragma unroll
        for (int m = 0; m < TS / 4; m++) {
            int ir = m * 4 + ig;
            o[(size_t)(ti * TS + ir) * VB + tj * TS + jl] = ev[ir * 65 + jl] * fj;
        }
    }
    if (ti != tj) {
        const float fi = invi[il];
        #pragma unroll
        for (int m = 0; m < TS / 4; m++) {
            int jr = m * 4 + jg;
            o[(size_t)(tj * TS + jr) * VB + ti * TS + il] = ev[il * 65 + jr] * fi;
        }
    }
}

extern "C" void kernel_launch(void* const* d_in, const int* in_sizes, int n_in,
                              void* d_out, int out_size) {
    const float* x = (const float*)d_in[0];   // (8,8,512,64) fp32
    const float* a = (const float*)d_in[1];   // (64,1) fp32
    float* out = (float*)d_out;               // (8,512,512) fp32

    const int smem_bytes = SMA_FLOATS * (int)sizeof(float);  // 52224 B
    cudaFuncSetAttribute(graph_learn_fused,
                         cudaFuncAttributeMaxDynamicSharedMemorySize, smem_bytes);

    dim3 grid(NPAIR, NB);   // (36, 8) = 288 blocks, one co-resident wave
    dim3 block(256, 1, 1);
    void* args[] = { (void*)&x, (void*)&a, (void*)&out };
    cudaLaunchCooperativeKernel((void*)graph_learn_fused, grid, block,
                                args, (size_t)smem_bytes, (cudaStream_t)0);
}

// round 12
// speedup vs baseline: 1.0028x; 1.0028x over previous
#include <cuda_runtime.h>

// Graph_Learn: S[n,i,j] = exp(relu(sum_f |xm[n,i,f]-xm[n,j,f]|*a[f])) / colsum_i
// N=8, T=8 (slice t=4), V=512, F=64. Output (8,512,512) fp32.
// Single cooperative persistent kernel. R12: 512-thread blocks (31 warps/SM,
// grid was occupancy-limiting) + 4 i-rows per outer iter (halves per-lane xj
// smem re-reads; crossbar was the binding pipe at L1=47%).

#define NB    8
#define TB    8
#define VB    512
#define FB    64
#define TS    64
#define NT    (VB / TS)                 // 8
#define NPAIR (NT * (NT + 1) / 2)       // 36
#define NBLK  (NPAIR * NB)              // 288 (<= 148 SMs * 2 CTA/SM = 296)
#define XJS   68                        // padded j-row stride (conflict-free)

typedef unsigned long long ull;

__device__ float g_partial[NB * NT * VB];   // [n][d][col], each slot written once
__device__ ull   g_bar = 0ull;              // monotone generation counter

__device__ __forceinline__ ull addx2(ull a, ull b) {
    ull r; asm("add.rn.f32x2 %0, %1, %2;" : "=l"(r) : "l"(a), "l"(b)); return r;
}
__device__ __forceinline__ ull fmax2k(ull a, ull b, ull c) {
    ull r; asm("fma.rn.f32x2 %0, %1, %2, %3;" : "=l"(r) : "l"(a), "l"(b), "l"(c)); return r;
}
__device__ __forceinline__ float sum2(ull a) {
    float lo, hi; asm("mov.b64 {%0, %1}, %2;" : "=f"(lo), "=f"(hi) : "l"(a)); return lo + hi;
}

// smem (floats): xi[64][64] | xjp[64][68] | ev[64][65] | sa[64] | ps[8][64] | invj[64] | invi[64]
#define SMA_XJP  (TS * FB)
#define SMA_EV   (SMA_XJP + TS * XJS)
#define SMA_A    (SMA_EV + TS * 65)
#define SMA_PS   (SMA_A + FB)
#define SMA_IJ   (SMA_PS + 8 * TS)
#define SMA_II   (SMA_IJ + TS)
#define SMA_FLOATS (SMA_II + TS)            // 13312 floats = 53248 B

__global__ __launch_bounds__(512, 2)
void graph_learn_fused(const float* __restrict__ x,
                       const float* __restrict__ a,
                       float* __restrict__ out) {
    extern __shared__ float sm[];
    float* xi   = sm;                 // [64][64]  (uniform/broadcast rows)
    float* xjp  = sm + SMA_XJP;       // [64][68]  (negated j-rows, per-lane)
    float* ev   = sm + SMA_EV;        // [64][65]
    float* sa   = sm + SMA_A;         // [64]
    float* ps   = sm + SMA_PS;        // [8][64]
    float* invj = sm + SMA_IJ;        // [64]
    float* invi = sm + SMA_II;        // [64]

    const int n   = blockIdx.y;
    const int tid = threadIdx.x;

    // decode upper-tri tile pair (ti <= tj)
    int ti = 0, rem = blockIdx.x;
    while (rem >= NT - ti) { rem -= NT - ti; ti++; }
    const int tj = ti + rem;

    const float* xbase = x + ((size_t)n * TB + TB / 2) * VB * FB;
    {
        const float4* si = (const float4*)(xbase + ti * TS * FB);
        const float4* sj = (const float4*)(xbase + tj * TS * FB);
        float4* xi4 = (float4*)xi;
        for (int k = tid; k < TS * FB / 4; k += 512) {
            xi4[k] = si[k];
            float4 v = sj[k];                       // negate j-rows on store
            int row = k >> 4, c4 = k & 15;
            float4* dst = (float4*)(xjp + row * XJS + c4 * 4);
            dst->x = -v.x; dst->y = -v.y; dst->z = -v.z; dst->w = -v.w;
        }
        if (tid < FB / 4) ((float4*)sa)[tid] = ((const float4*)a)[tid];
    }
    __syncthreads();

    const int jl = tid & (TS - 1);   // j within tile (0..63); warp spans 32 consecutive
    const int ig = tid >> 6;         // i-group (0..7), warp-uniform

    const ull ABSM = 0x7FFFFFFF7FFFFFFFULL;
    const ulonglong2* sa2 = (const ulonglong2*)sa;
    const ulonglong2* xr  = (const ulonglong2*)(xjp + jl * XJS);  // per-lane
    float csum = 0.f;

    // mainloop: 2 outer iters x 4 i-rows, 8 packed accumulator chains
    #pragma unroll 1
    for (int it = 0; it < 2; it++) {
        const int ib = it * 32 + ig * 4;         // warp-uniform row base
        const ulonglong2* r0 = (const ulonglong2*)(xi + (ib + 0) * FB);
        const ulonglong2* r1 = (const ulonglong2*)(xi + (ib + 1) * FB);
        const ulonglong2* r2 = (const ulonglong2*)(xi + (ib + 2) * FB);
        const ulonglong2* r3 = (const ulonglong2*)(xi + (ib + 3) * FB);
        ull a00 = 0, a01 = 0, a10 = 0, a11 = 0;
        ull a20 = 0, a21 = 0, a30 = 0, a31 = 0;
        #pragma unroll
        for (int k = 0; k < FB / 4; k++) {
            ulonglong2 av  = sa2[k];
            ulonglong2 xjv = xr[k];
            ulonglong2 v0 = r0[k], v1 = r1[k], v2 = r2[k], v3 = r3[k];
            ull d;
            d = addx2(v0.x, xjv.x) & ABSM; a00 = fmax2k(d, av.x, a00);
            d = addx2(v0.y, xjv.y) & ABSM; a01 = fmax2k(d, av.y, a01);
            d = addx2(v1.x, xjv.x) & ABSM; a10 = fmax2k(d, av.x, a10);
            d = addx2(v1.y, xjv.y) & ABSM; a11 = fmax2k(d, av.y, a11);
            d = addx2(v2.x, xjv.x) & ABSM; a20 = fmax2k(d, av.x, a20);
            d = addx2(v2.y, xjv.y) & ABSM; a21 = fmax2k(d, av.y, a21);
            d = addx2(v3.x, xjv.x) & ABSM; a30 = fmax2k(d, av.x, a30);
            d = addx2(v3.y, xjv.y) & ABSM; a31 = fmax2k(d, av.y, a31);
        }
        float e0 = __expf(fmaxf(sum2(a00) + sum2(a01), 0.f));
        float e1 = __expf(fmaxf(sum2(a10) + sum2(a11), 0.f));
        float e2 = __expf(fmaxf(sum2(a20) + sum2(a21), 0.f));
        float e3 = __expf(fmaxf(sum2(a30) + sum2(a31), 0.f));
        ev[(ib + 0) * 65 + jl] = e0;
        ev[(ib + 1) * 65 + jl] = e1;
        ev[(ib + 2) * 65 + jl] = e2;
        ev[(ib + 3) * 65 + jl] = e3;
        csum += (e0 + e1) + (e2 + e3);
    }

    // direct partial: rows ti-range, columns tj*64+jl -> slot [n][ti]
    ps[ig * TS + jl] = csum;
    __syncthreads();
    if (tid < TS) {
        float t = 0.f;
        #pragma unroll
        for (int g = 0; g < 8; g++) t += ps[g * TS + tid];
        g_partial[(n * NT + ti) * VB + tj * TS + tid] = t;
    }

    const int il = tid & (TS - 1);
    const int jg = tid >> 6;             // 0..7
    if (ti != tj) {
        // transposed partial: rows tj-range, columns ti*64+il -> slot [n][tj]
        float rsum = 0.f;
        #pragma unroll
        for (int m = 0; m < TS / 8; m++) {
            rsum += ev[il * 65 + (m * 8 + jg)];   // stride-65: conflict-free
        }
        __syncthreads();                          // ps readers done
        ps[jg * TS + il] = rsum;
        __syncthreads();
        if (tid < TS) {
            float t = 0.f;
            #pragma unroll
            for (int g = 0; g < 8; g++) t += ps[g * TS + tid];
            g_partial[(n * NT + tj) * VB + ti * TS + tid] = t;
        }
    }

    // ---- software grid barrier (generation counting, replay-safe;
    //      co-residency guaranteed by cooperative launch) ----
    __threadfence();
    __syncthreads();
    if (tid == 0) {
        ull my = atomicAdd(&g_bar, 1ull);
        ull target = (my / NBLK + 1ull) * (ull)NBLK;
        while (*((volatile ull*)&g_bar) < target) { __nanosleep(32); }
    }
    __syncthreads();
    __threadfence();

    // ---- column sums -> inverse norms ----
    if (tid < TS) {
        const float* p = g_partial + n * NT * VB + tj * TS + tid;
        float s = 0.f;
        #pragma unroll
        for (int d = 0; d < NT; d++) s += p[d * VB];
        invj[tid] = 1.0f / s;
    } else if (tid < 2 * TS && ti != tj) {
        const float* p = g_partial + n * NT * VB + ti * TS + (tid - TS);
        float s = 0.f;
        #pragma unroll
        for (int d = 0; d < NT; d++) s += p[d * VB];
        invi[tid - TS] = 1.0f / s;
    }
    __syncthreads();

    // ---- normalized writes (single gmem write per element) ----
    float* o = out + (size_t)n * VB * VB;
    {
        const float fj = invj[jl];
        #pragma unroll
        for (int m = 0; m < TS / 8; m++) {
            int ir = m * 8 + ig;
            o[(size_t)(ti * TS + ir) * VB + tj * TS + jl] = ev[ir * 65 + jl] * fj;
        }
    }
    if (ti != tj) {
        const float fi = invi[il];
        #pragma unroll
        for (int m = 0; m < TS / 8; m++) {
            int jr = m * 8 + jg;
            o[(size_t)(tj * TS + jr) * VB + ti * TS + il] = ev[il * 65 + jr] * fi;
        }
    }
}

extern "C" void kernel_launch(void* const* d_in, const int* in_sizes, int n_in,
                              void* d_out, int out_size) {
    const float* x = (const float*)d_in[0];   // (8,8,512,64) fp32
    const float* a = (const float*)d_in[1];   // (64,1) fp32
    float* out = (float*)d_out;               // (8,512,512) fp32

    const int smem_bytes = SMA_FLOATS * (int)sizeof(float);  // 53248 B
    cudaFuncSetAttribute(graph_learn_fused,
                         cudaFuncAttributeMaxDynamicSharedMemorySize, smem_bytes);

    dim3 grid(NPAIR, NB);   // (36, 8) = 288 blocks, one co-resident wave
    dim3 block(512, 1, 1);
    void* args[] = { (void*)&x, (void*)&a, (void*)&out };
    cudaLaunchCooperativeKernel((void*)graph_learn_fused, grid, block,
                                args, (size_t)smem_bytes, (cudaStream_t)0);
}